// round 5
// baseline (speedup 1.0000x reference)
#include <cuda_runtime.h>
#include <math.h>

// ---------------------------------------------------------------------------
// TAM forward, GB300.  Shapes fixed: b=8, t=16, c=256, h=w=28 (784 px).
//   x   : [8,16,256,28,28] f32
//   W1  : [32,16]   W2 : [7,32]   Wl1 : [64,256,7]   Wl2 : [256,64,1]
//   out : [128,256,28,28] f32  (same linear layout as x)
// Pipeline: pool -> conv1(L) -> gate(G kernel + L local) -> main gated dw-conv
// ---------------------------------------------------------------------------

#define B    8
#define T    16
#define C    256
#define HW   784
#define HW4  196           // float4 per plane
#define CO   64            // c/4

__device__ float g_pooled[B * C * T];      // [b,c,t]
__device__ float g_y[B * CO * T];          // [b,o,t]
__device__ float g_ker[B * C * 8];         // [b,c,k] (k padded to 8)
__device__ float g_loc[B * C * T];         // [b,c,t]

// ---------------------------------------------------------------------------
// Kernel 1: pooled[b,c,t] = mean_{hw} x[b,t,c,hw].  One warp per plane.
// grid = 32768/8 = 4096 blocks, 256 threads (8 warps).
// ---------------------------------------------------------------------------
__global__ void __launch_bounds__(256) pool_kernel(const float* __restrict__ x) {
    const int warp = threadIdx.x >> 5;
    const int lane = threadIdx.x & 31;
    const int p = blockIdx.x * 8 + warp;           // p = (b*16+t)*256 + c
    const float4* xp = reinterpret_cast<const float4*>(x) + (size_t)p * HW4;

    float s = 0.f;
#pragma unroll
    for (int j = 0; j < 7; j++) {
        int idx = lane + 32 * j;
        if (idx < HW4) {
            float4 v = xp[idx];
            s += (v.x + v.y) + (v.z + v.w);
        }
    }
#pragma unroll
    for (int off = 16; off; off >>= 1) s += __shfl_xor_sync(0xFFFFFFFFu, s, off);

    if (lane == 0) {
        int c = p & 255;
        int bt = p >> 8;
        int t = bt & 15;
        int b = bt >> 4;
        g_pooled[(b * C + c) * T + t] = s * (1.f / 784.f);
    }
}

// ---------------------------------------------------------------------------
// Kernel 2a: y[b,o,t] = tanh( sum_{i,k} Wl1[o,i,k] * pooled_pad[b,i,t+k-3] )
// grid = b*64 = 512 blocks, 256 threads (one thread per input channel i).
// ---------------------------------------------------------------------------
__global__ void __launch_bounds__(256) conv1_kernel(const float* __restrict__ Wl1) {
    const int b = blockIdx.x >> 6;
    const int o = blockIdx.x & 63;
    const int i = threadIdx.x;

    const float* pr = &g_pooled[(b * C + i) * T];
    float pp[T + 6];
#pragma unroll
    for (int t = 0; t < T + 6; t++) {
        int tt = t - 3;
        pp[t] = (tt >= 0 && tt < T) ? pr[tt] : 0.f;
    }
    const float* w = &Wl1[(o * C + i) * 7];
    float wk[7];
#pragma unroll
    for (int k = 0; k < 7; k++) wk[k] = w[k];

    float acc[T];
#pragma unroll
    for (int t = 0; t < T; t++) {
        float s = 0.f;
#pragma unroll
        for (int k = 0; k < 7; k++) s = fmaf(wk[k], pp[t + k], s);
        acc[t] = s;
    }
    // warp reduce each of the 16 sums
#pragma unroll
    for (int off = 16; off; off >>= 1) {
#pragma unroll
        for (int t = 0; t < T; t++) acc[t] += __shfl_xor_sync(0xFFFFFFFFu, acc[t], off);
    }
    __shared__ float sm[8][T];
    const int warp = i >> 5, lane = i & 31;
    if (lane < T) sm[warp][lane] = acc[lane];
    __syncthreads();
    if (i < T) {
        float s = 0.f;
#pragma unroll
        for (int w2 = 0; w2 < 8; w2++) s += sm[w2][i];
        g_y[(b * CO + o) * T + i] = tanhf(s);
    }
}

// ---------------------------------------------------------------------------
// Kernel 2b: per-(b,c) warp:
//   G: g[u]=tanh(sum_t W1[u,t]*p[t]); logits[k]=sum_u W2[k,u]*g[u]; softmax -> g_ker
//   L: local[t]=sigmoid(sum_o Wl2[c,o]*y[b,o,t]) -> g_loc
// grid = 2048 warps / 8 = 256 blocks, 256 threads.
// ---------------------------------------------------------------------------
__global__ void __launch_bounds__(256) gate_kernel(const float* __restrict__ W1,
                                                   const float* __restrict__ W2,
                                                   const float* __restrict__ Wl2) {
    const int gw = blockIdx.x * 8 + (threadIdx.x >> 5);
    const int lane = threadIdx.x & 31;
    const int b = gw >> 8, c = gw & 255;

    const float* pr = &g_pooled[(b * C + c) * T];
    float p = (lane < T) ? pr[lane] : 0.f;

    // --- G branch ---
    float g = 0.f;
#pragma unroll
    for (int t = 0; t < T; t++) {
        float pt = __shfl_sync(0xFFFFFFFFu, p, t);
        g = fmaf(W1[lane * T + t], pt, g);
    }
    g = tanhf(g);

    float lg[7];
#pragma unroll
    for (int k = 0; k < 7; k++) {
        float s = W2[k * 32 + lane] * g;
#pragma unroll
        for (int off = 16; off; off >>= 1) s += __shfl_xor_sync(0xFFFFFFFFu, s, off);
        lg[k] = s;
    }
    float m = lg[0];
#pragma unroll
    for (int k = 1; k < 7; k++) m = fmaxf(m, lg[k]);
    float den = 0.f;
#pragma unroll
    for (int k = 0; k < 7; k++) { lg[k] = expf(lg[k] - m); den += lg[k]; }
    float inv = 1.f / den;
    if (lane < 7) g_ker[(b * C + c) * 8 + lane] = lg[lane] * inv;

    // --- L branch ---
    float acc[T];
#pragma unroll
    for (int t = 0; t < T; t++) acc[t] = 0.f;
#pragma unroll
    for (int oo = 0; oo < 2; oo++) {
        int o = lane + 32 * oo;
        float w = Wl2[c * CO + o];
        const float* yr = &g_y[(b * CO + o) * T];
#pragma unroll
        for (int t = 0; t < T; t++) acc[t] = fmaf(w, yr[t], acc[t]);
    }
#pragma unroll
    for (int off = 16; off; off >>= 1) {
#pragma unroll
        for (int t = 0; t < T; t++) acc[t] += __shfl_xor_sync(0xFFFFFFFFu, acc[t], off);
    }
    if (lane < T) g_loc[(b * C + c) * T + lane] = 1.f / (1.f + expf(-acc[lane]));
}

// ---------------------------------------------------------------------------
// Kernel 3 (the heavy one): for each (b,c,pixel4):
//   gated[t] = x[b,t,c,px] * local[b,c,t]
//   out[b,t,c,px] = sum_k kernel[b,c,k] * gated[t+k-3]   (zero pad)
// Reads x once (coalesced float4, MLP=16), writes out once via streaming
// stores (out has zero reuse; keep x resident in L2 instead).
// grid = 2048 (b*c), 196 threads (one float4 per thread).
// ---------------------------------------------------------------------------
__global__ void __launch_bounds__(196) tam_main_kernel(const float* __restrict__ x,
                                                       float* __restrict__ out) {
    const int bc = blockIdx.x;                 // b*256 + c
    const int b = bc >> 8, c = bc & 255;

    __shared__ float sk[7], sl[T];
    if (threadIdx.x < 7)  sk[threadIdx.x] = g_ker[bc * 8 + threadIdx.x];
    if (threadIdx.x < T)  sl[threadIdx.x] = g_loc[bc * T + threadIdx.x];
    __syncthreads();

    float ker[7], loc[T];
#pragma unroll
    for (int k = 0; k < 7; k++) ker[k] = sk[k];
#pragma unroll
    for (int t = 0; t < T; t++) loc[t] = sl[t];

    const size_t base = ((size_t)(b * T) * C + c) * HW4;   // float4 offset of (b,t=0,c)
    const size_t stride = (size_t)C * HW4;                  // float4 stride per t
    const float4* xp = reinterpret_cast<const float4*>(x);
    float4* op = reinterpret_cast<float4*>(out);
    const int pix = threadIdx.x;

    float4 gt[T];
#pragma unroll
    for (int t = 0; t < T; t++) {
        float4 v = xp[base + (size_t)t * stride + pix];
        float lt = loc[t];
        gt[t].x = v.x * lt; gt[t].y = v.y * lt;
        gt[t].z = v.z * lt; gt[t].w = v.w * lt;
    }
#pragma unroll
    for (int to = 0; to < T; to++) {
        float4 a = make_float4(0.f, 0.f, 0.f, 0.f);
#pragma unroll
        for (int k = 0; k < 7; k++) {
            int tt = to + k - 3;
            if (tt >= 0 && tt < T) {          // compile-time resolved
                float kv = ker[k];
                a.x = fmaf(kv, gt[tt].x, a.x);
                a.y = fmaf(kv, gt[tt].y, a.y);
                a.z = fmaf(kv, gt[tt].z, a.z);
                a.w = fmaf(kv, gt[tt].w, a.w);
            }
        }
        __stcs(&op[base + (size_t)to * stride + pix], a);   // evict-first store
    }
}

// ---------------------------------------------------------------------------
extern "C" void kernel_launch(void* const* d_in, const int* in_sizes, int n_in,
                              void* d_out, int out_size) {
    const float* x   = (const float*)d_in[0];
    const float* W1  = (const float*)d_in[1];
    const float* W2  = (const float*)d_in[2];
    const float* Wl1 = (const float*)d_in[3];
    const float* Wl2 = (const float*)d_in[4];
    float* out = (float*)d_out;

    pool_kernel<<<(B * T * C) / 8, 256>>>(x);        // 4096 blocks
    conv1_kernel<<<B * CO, 256>>>(Wl1);              // 512 blocks
    gate_kernel<<<(B * C) / 8, 256>>>(W1, W2, Wl2);  // 256 blocks
    tam_main_kernel<<<B * C, 196>>>(x, out);         // 2048 blocks
}

// round 10
// speedup vs baseline: 1.1329x; 1.1329x over previous
#include <cuda_runtime.h>
#include <math.h>

// ---------------------------------------------------------------------------
// TAM forward, GB300.  Shapes fixed: b=8, t=16, c=256, h=w=28 (784 px).
//   x   : [8,16,256,28,28] f32
//   W1  : [32,16]   W2 : [7,32]   Wl1 : [64,256,7]   Wl2 : [256,64,1]
//   out : [128,256,28,28] f32
// Pipeline (3 launches): pool -> conv1(L) -> main (gate fused + gated dw-conv)
// ---------------------------------------------------------------------------

#define B     8
#define T     16
#define C     256
#define HW4   196            // float4 per plane
#define SLAB  50176          // float4 per (b,t) slab  = C*HW4
#define CO    64             // c/4

__device__ float g_pooled[B * C * T];      // [b,c,t]
__device__ float g_y[B * CO * T];          // [b,o,t]

// ---------------------------------------------------------------------------
// Kernel 1: pooled[b,c,t] = mean_{hw} x[b,t,c,hw].  One warp per plane.
// ---------------------------------------------------------------------------
__global__ void __launch_bounds__(256) pool_kernel(const float* __restrict__ x) {
    const int warp = threadIdx.x >> 5;
    const int lane = threadIdx.x & 31;
    const int p = blockIdx.x * 8 + warp;           // p = (b*16+t)*256 + c
    const float4* xp = reinterpret_cast<const float4*>(x) + (size_t)p * HW4;

    float s = 0.f;
#pragma unroll
    for (int j = 0; j < 7; j++) {
        int idx = lane + 32 * j;
        if (idx < HW4) {
            float4 v = xp[idx];
            s += (v.x + v.y) + (v.z + v.w);
        }
    }
#pragma unroll
    for (int off = 16; off; off >>= 1) s += __shfl_xor_sync(0xFFFFFFFFu, s, off);

    if (lane == 0) {
        int c = p & 255;
        int bt = p >> 8;
        int t = bt & 15;
        int b = bt >> 4;
        g_pooled[(b * C + c) * T + t] = s * (1.f / 784.f);
    }
}

// ---------------------------------------------------------------------------
// Kernel 2: y[b,o,t] = tanh( sum_{i,k} Wl1[o,i,k] * pooled_pad[b,i,t+k-3] )
// grid = b*64 = 512 blocks, 256 threads (one thread per input channel i).
// ---------------------------------------------------------------------------
__global__ void __launch_bounds__(256) conv1_kernel(const float* __restrict__ Wl1) {
    const int b = blockIdx.x >> 6;
    const int o = blockIdx.x & 63;
    const int i = threadIdx.x;

    const float* pr = &g_pooled[(b * C + i) * T];
    float pp[T + 6];
#pragma unroll
    for (int t = 0; t < T + 6; t++) {
        int tt = t - 3;
        pp[t] = (tt >= 0 && tt < T) ? pr[tt] : 0.f;
    }
    const float* w = &Wl1[(o * C + i) * 7];
    float wk[7];
#pragma unroll
    for (int k = 0; k < 7; k++) wk[k] = w[k];

    float acc[T];
#pragma unroll
    for (int t = 0; t < T; t++) {
        float s = 0.f;
#pragma unroll
        for (int k = 0; k < 7; k++) s = fmaf(wk[k], pp[t + k], s);
        acc[t] = s;
    }
#pragma unroll
    for (int off = 16; off; off >>= 1) {
#pragma unroll
        for (int t = 0; t < T; t++) acc[t] += __shfl_xor_sync(0xFFFFFFFFu, acc[t], off);
    }
    __shared__ float sm[8][T];
    const int warp = i >> 5, lane = i & 31;
    if (lane < T) sm[warp][lane] = acc[lane];
    __syncthreads();
    if (i < T) {
        float s = 0.f;
#pragma unroll
        for (int w2 = 0; w2 < 8; w2++) s += sm[w2][i];
        g_y[(b * CO + o) * T + i] = tanhf(s);
    }
}

// ---------------------------------------------------------------------------
// Kernel 3: gate (fused) + gated depthwise temporal conv.
// Flat mapping: column s = c*196 + pix within a b.  256 cols per block.
// grid = 8 * 196 = 1568 blocks (reversed for L2 reuse of pool's tail),
// block = 256 threads.  Warps 0-2 compute gate for the <=3 channels spanned.
// ---------------------------------------------------------------------------
__global__ void __launch_bounds__(256) tam_main_kernel(const float* __restrict__ x,
                                                       const float* __restrict__ W1,
                                                       const float* __restrict__ W2,
                                                       const float* __restrict__ Wl2,
                                                       float* __restrict__ out) {
    const int blk = (int)gridDim.x - 1 - blockIdx.x;   // reverse order
    const int b  = blk / 196;
    const int j  = blk - b * 196;
    const int s0 = j * 256;
    const int c_first = s0 / HW4;

    __shared__ float sk[3][8];    // kernel[ci][k]
    __shared__ float sl[3][T];    // local[ci][t]

    const int warp = threadIdx.x >> 5;
    const int lane = threadIdx.x & 31;

    if (warp < 3) {
        const int c = c_first + warp;
        if (c < C) {
            // pooled row in lanes 0..15
            float p = (lane < T) ? g_pooled[(b * C + c) * T + lane] : 0.f;

            // --- G branch: 7-tap softmax kernel ---
            float g = 0.f;
#pragma unroll
            for (int t = 0; t < T; t++) {
                float pt = __shfl_sync(0xFFFFFFFFu, p, t);
                g = fmaf(W1[lane * T + t], pt, g);
            }
            g = tanhf(g);

            float lg[7];
#pragma unroll
            for (int k = 0; k < 7; k++) {
                float s = W2[k * 32 + lane] * g;
#pragma unroll
                for (int off = 16; off; off >>= 1) s += __shfl_xor_sync(0xFFFFFFFFu, s, off);
                lg[k] = s;
            }
            float m = lg[0];
#pragma unroll
            for (int k = 1; k < 7; k++) m = fmaxf(m, lg[k]);
            float den = 0.f;
#pragma unroll
            for (int k = 0; k < 7; k++) { lg[k] = expf(lg[k] - m); den += lg[k]; }
            float inv = 1.f / den;
            if (lane < 7) sk[warp][lane] = lg[lane] * inv;

            // --- L branch: sigmoid( Wl2[c,:] . y[b,:,t] ) ---
            if (lane < T) {
                const float* yb = &g_y[b * CO * T];
                const float* wr = &Wl2[c * CO];
                float acc = 0.f;
#pragma unroll
                for (int o = 0; o < CO; o++)
                    acc = fmaf(wr[o], yb[o * T + lane], acc);
                sl[warp][lane] = 1.f / (1.f + expf(-acc));
            }
        }
    }
    __syncthreads();

    const int s  = s0 + threadIdx.x;        // column within b-slab
    const int c  = s / HW4;                 // constant divisor -> mul/shift
    const int ci = c - c_first;             // 0..2

    float ker[7], loc[T];
#pragma unroll
    for (int k = 0; k < 7; k++) ker[k] = sk[ci][k];
#pragma unroll
    for (int t = 0; t < T; t++) loc[t] = sl[ci][t];

    const size_t base = (size_t)(b * T) * SLAB + s;    // float4 index of (b,t=0,s)
    const float4* xp = reinterpret_cast<const float4*>(x);
    float4* op = reinterpret_cast<float4*>(out);

    float4 gt[T];
#pragma unroll
    for (int t = 0; t < T; t++) {
        float4 v = xp[base + (size_t)t * SLAB];
        float lt = loc[t];
        gt[t].x = v.x * lt; gt[t].y = v.y * lt;
        gt[t].z = v.z * lt; gt[t].w = v.w * lt;
    }
#pragma unroll
    for (int to = 0; to < T; to++) {
        float4 a = make_float4(0.f, 0.f, 0.f, 0.f);
#pragma unroll
        for (int k = 0; k < 7; k++) {
            int tt = to + k - 3;
            if (tt >= 0 && tt < T) {          // compile-time resolved
                float kv = ker[k];
                a.x = fmaf(kv, gt[tt].x, a.x);
                a.y = fmaf(kv, gt[tt].y, a.y);
                a.z = fmaf(kv, gt[tt].z, a.z);
                a.w = fmaf(kv, gt[tt].w, a.w);
            }
        }
        __stcs(&op[base + (size_t)to * SLAB], a);      // evict-first store
    }
}

// ---------------------------------------------------------------------------
extern "C" void kernel_launch(void* const* d_in, const int* in_sizes, int n_in,
                              void* d_out, int out_size) {
    const float* x   = (const float*)d_in[0];
    const float* W1  = (const float*)d_in[1];
    const float* W2  = (const float*)d_in[2];
    const float* Wl1 = (const float*)d_in[3];
    const float* Wl2 = (const float*)d_in[4];
    float* out = (float*)d_out;

    pool_kernel<<<(B * T * C) / 8, 256>>>(x);             // 4096 blocks
    conv1_kernel<<<B * CO, 256>>>(Wl1);                   // 512 blocks
    tam_main_kernel<<<B * 196, 256>>>(x, W1, W2, Wl2, out);  // 1568 blocks
}